// round 17
// baseline (speedup 1.0000x reference)
#include <cuda_runtime.h>
#include <cuda_fp16.h>
#include <math.h>
#include <stdint.h>

// Problem dims (fixed)
#define B_   2
#define T_   4096
#define D_   2048
#define H_   32
#define DK   64
#define BS_  128
#define NB   (T_ / BS_)     // 32
#define M_   (B_ * T_)      // 8192

// ---------------------------------------------------------------------------
// Scratch device globals (fp16 pipeline throughout)
// ---------------------------------------------------------------------------
__device__ __half g_qkv[3][(size_t)M_ * D_];   // Q(prescaled by 1/8), K, V
__device__ __half g_xh [(size_t)M_ * D_];
__device__ __half g_aoh[(size_t)M_ * D_];
__device__ __half g_wh [4][(size_t)D_ * D_];

// ---------------------------------------------------------------------------
// helpers
// ---------------------------------------------------------------------------
__device__ __forceinline__ uint32_t smem_to_u32(const void* p) {
    uint32_t a;
    asm("{ .reg .u64 t; cvta.to.shared.u64 t, %1; cvt.u32.u64 %0, t; }" : "=r"(a) : "l"(p));
    return a;
}
__device__ __forceinline__ uint32_t h2_to_u32(__half2 v) {
    return *reinterpret_cast<uint32_t*>(&v);
}
__device__ __forceinline__ void cp16(uint32_t saddr, const void* gptr) {
    asm volatile("cp.async.cg.shared.global [%0], [%1], 16;" :: "r"(saddr), "l"(gptr));
}
#define CP_COMMIT() asm volatile("cp.async.commit_group;" ::: "memory")

#define LDSM4(r, addr) \
    asm volatile("ldmatrix.sync.aligned.m8n8.x4.shared.b16 {%0,%1,%2,%3}, [%4];" \
        : "=r"((r)[0]), "=r"((r)[1]), "=r"((r)[2]), "=r"((r)[3]) : "r"(addr))

#define LDSM4T(r, addr) \
    asm volatile("ldmatrix.sync.aligned.m8n8.x4.trans.shared.b16 {%0,%1,%2,%3}, [%4];" \
        : "=r"((r)[0]), "=r"((r)[1]), "=r"((r)[2]), "=r"((r)[3]) : "r"(addr))

#define MMAF16(c, a, b0v, b1v) \
    asm volatile("mma.sync.aligned.m16n8k16.row.col.f32.f16.f16.f32 " \
        "{%0,%1,%2,%3}, {%4,%5,%6,%7}, {%8,%9}, {%0,%1,%2,%3};" \
        : "+f"((c)[0]), "+f"((c)[1]), "+f"((c)[2]), "+f"((c)[3]) \
        : "r"((a)[0]), "r"((a)[1]), "r"((a)[2]), "r"((a)[3]), "r"(b0v), "r"(b1v))

// ---------------------------------------------------------------------------
// fp16 tensor-core GEMM core (NT): C = A x B^T, fp32 accum, output scaled.
// CTA tile 128x64, BK=64, 128 threads, 2 stages, frag double-buffer, 3 CTAs/SM.
// ---------------------------------------------------------------------------
#define ROWB    144
#define ATILEB  (128 * ROWB)
#define BTILEB  (64  * ROWB)
#define STAGEB  (ATILEB + BTILEB)            // 27648
#define GSMEM   (2 * STAGEB)                 // 55296

template <typename OutT>
__device__ __forceinline__ void gemm_core(
    const __half* __restrict__ A, const __half* __restrict__ Bw,
    OutT* __restrict__ C, int M, int N, int K, float oscale, char* smem_raw)
{
    const uint32_t sbase = smem_to_u32(smem_raw);

    const int tid  = threadIdx.x;
    const int lane = tid & 31;
    const int warp = tid >> 5;
    const int wm   = warp & 1;
    const int wn   = warp >> 1;
    const int bm   = blockIdx.y * 128;
    const int bn   = blockIdx.x * 64;
    const int NT   = K / 64;

    const char* A0 = (const char*)(A  + (size_t)bm * K);
    const char* B0 = (const char*)(Bw + (size_t)bn * K);

    const uint32_t aOff = (uint32_t)((wm * 64 + (lane & 15)) * ROWB + (lane >> 4) * 16);
    const uint32_t bOff = (uint32_t)((wn * 32 + (lane & 7) + ((lane >> 4) & 1) * 8) * ROWB
                                     + ((lane >> 3) & 1) * 16);

    float acc[4][4][4];
#pragma unroll
    for (int mt = 0; mt < 4; ++mt)
#pragma unroll
        for (int nt = 0; nt < 4; ++nt)
#pragma unroll
            for (int e = 0; e < 4; ++e) acc[mt][nt][e] = 0.0f;

    auto load_stage = [&](int kt, int s) {
        const uint32_t st = sbase + (uint32_t)s * STAGEB;
        const size_t kbyte = (size_t)kt * 128;
#pragma unroll
        for (int j = 0; j < 8; ++j) {
            int c  = tid + j * 128;
            int r  = c >> 3;
            int kb = (c & 7) * 16;
            cp16(st + (uint32_t)(r * ROWB + kb),
                 A0 + (size_t)r * K * 2 + kbyte + kb);
        }
#pragma unroll
        for (int j = 0; j < 4; ++j) {
            int c  = tid + j * 128;
            int r  = c >> 3;
            int kb = (c & 7) * 16;
            cp16(st + ATILEB + (uint32_t)(r * ROWB + kb),
                 B0 + (size_t)r * K * 2 + kbyte + kb);
        }
        CP_COMMIT();
    };

    load_stage(0, 0);

#define LDFRAGS(buf, ks) do { \
    _Pragma("unroll") \
    for (int _mt = 0; _mt < 4; ++_mt) \
        LDSM4(ah[buf][_mt], stA + aOff + _mt * (16 * ROWB) + (ks) * 32); \
    _Pragma("unroll") \
    for (int _np = 0; _np < 2; ++_np) \
        LDSM4(bh[buf][_np], stB + bOff + _np * (16 * ROWB) + (ks) * 32); \
} while (0)

    for (int kt = 0; kt < NT; ++kt) {
        if (kt + 1 < NT) {
            load_stage(kt + 1, (kt + 1) & 1);
            asm volatile("cp.async.wait_group 1;" ::: "memory");
        } else {
            asm volatile("cp.async.wait_group 0;" ::: "memory");
        }
        __syncthreads();

        const uint32_t st  = sbase + (uint32_t)(kt & 1) * STAGEB;
        const uint32_t stA = st;
        const uint32_t stB = st + ATILEB;

        uint32_t ah[2][4][4], bh[2][2][4];
        LDFRAGS(0, 0);

#pragma unroll
        for (int ks = 0; ks < 4; ++ks) {
            const int cur = ks & 1;
            const int nxt = cur ^ 1;
            if (ks < 3) {
                switch (ks + 1) {
                    case 1: LDFRAGS(nxt, 1); break;
                    case 2: LDFRAGS(nxt, 2); break;
                    default: LDFRAGS(nxt, 3); break;
                }
            }
#pragma unroll
            for (int mt = 0; mt < 4; ++mt)
#pragma unroll
                for (int np = 0; np < 2; ++np) {
                    MMAF16(acc[mt][2 * np],     ah[cur][mt], bh[cur][np][0], bh[cur][np][1]);
                    MMAF16(acc[mt][2 * np + 1], ah[cur][mt], bh[cur][np][2], bh[cur][np][3]);
                }
        }

        __syncthreads();
    }

    const int rbase = bm + wm * 64 + (lane >> 2);
    const int cbase = bn + wn * 32 + (lane & 3) * 2;
#pragma unroll
    for (int mt = 0; mt < 4; ++mt) {
#pragma unroll
        for (int nt = 0; nt < 4; ++nt) {
            int grow = rbase + mt * 16;
            int gcol = cbase + nt * 8;
            if constexpr (sizeof(OutT) == 4) {
                *(float2*)((float*)C + (size_t)grow * N + gcol) =
                    make_float2(acc[mt][nt][0], acc[mt][nt][1]);
                *(float2*)((float*)C + (size_t)(grow + 8) * N + gcol) =
                    make_float2(acc[mt][nt][2], acc[mt][nt][3]);
            } else {
                *(__half2*)((__half*)C + (size_t)grow * N + gcol) =
                    __floats2half2_rn(acc[mt][nt][0] * oscale, acc[mt][nt][1] * oscale);
                *(__half2*)((__half*)C + (size_t)(grow + 8) * N + gcol) =
                    __floats2half2_rn(acc[mt][nt][2] * oscale, acc[mt][nt][3] * oscale);
            }
        }
    }
#undef LDFRAGS
}

// Fused QKV: blockIdx.z selects weight panel and output buffer.
// Q (z==0) is pre-scaled by 0.125 (power of two -> exact).
__global__ __launch_bounds__(128, 3) void gemm_qkv(
    const __half* __restrict__ A, const __half* __restrict__ WhBase,
    __half* __restrict__ QKVBase, int M, int N, int K)
{
    extern __shared__ __align__(16) char smem_raw[];
    const int z = blockIdx.z;
    const float sc = (z == 0) ? 0.125f : 1.0f;
    gemm_core<__half>(A, WhBase + (size_t)z * D_ * D_,
                      QKVBase + (size_t)z * M_ * D_, M, N, K, sc, smem_raw);
}

// Single GEMM, fp32 out (final projection).
__global__ __launch_bounds__(128, 3) void gemm_out(
    const __half* __restrict__ A, const __half* __restrict__ Bw,
    float* __restrict__ C, int M, int N, int K)
{
    extern __shared__ __align__(16) char smem_raw[];
    gemm_core<float>(A, Bw, C, M, N, K, 1.0f, smem_raw);
}

// ---------------------------------------------------------------------------
// fp32 -> fp16 conversion, single launch over 5 tensors (x + 4 weights).
// ---------------------------------------------------------------------------
struct ConvJob { const float4* src; __half2* dst; int n4; };
struct ConvJobs { ConvJob j[5]; };

__global__ void conv_all_kernel(ConvJobs jobs)
{
    const ConvJob jb = jobs.j[blockIdx.y];
    int i = blockIdx.x * blockDim.x + threadIdx.x;
    if (i >= jb.n4) return;
    float4 v = jb.src[i];
    jb.dst[2 * i]     = __halves2half2(__float2half(v.x), __float2half(v.y));
    jb.dst[2 * i + 1] = __halves2half2(__float2half(v.z), __float2half(v.w));
}

// ---------------------------------------------------------------------------
// Tensor-core sliding-window flash attention, max-free softmax.
// Q is pre-scaled by 1/8, so S needs no scale here. Mask via one unsigned cmp.
// ---------------------------------------------------------------------------
#define QROWB   144
#define KVROWB  144
#define QTILE   (128 * QROWB)            // 18432
#define KVTILE  (64 * KVROWB)            // 9216
#define SWSTAGE (2 * KVTILE)             // 18432 (K+V)
#define SWSMEM  (QTILE + 2 * SWSTAGE)    // 55296

__global__ __launch_bounds__(256, 2) void swa_tc(
    const __half* __restrict__ Qh, const __half* __restrict__ Kh,
    const __half* __restrict__ Vh, __half* __restrict__ Oh)
{
    extern __shared__ __align__(16) char sm[];
    const uint32_t sb  = smem_to_u32(sm);
    const uint32_t Qs  = sb;
    const uint32_t KVs = sb + QTILE;

    const int i = blockIdx.x, h = blockIdx.y, b = blockIdx.z;
    const int tid = threadIdx.x, lane = tid & 31, w = tid >> 5;
    const int rbase = 16 * w;
    const size_t bh = (size_t)b * T_ * D_ + (size_t)h * DK;
    const int qrow0 = i * BS_;

    auto load_kv = [&](int c0, int s) {
        uint32_t Ks  = KVs + (uint32_t)s * SWSTAGE;
        uint32_t Vs2 = Ks + KVTILE;
        int tk0 = qrow0 - BS_ + c0;
#pragma unroll
        for (int j = 0; j < 2; ++j) {
            int c = tid + j * 256;
            int r = c >> 3;
            int kb = (c & 7) * 16;
            cp16(Ks + (uint32_t)(r * KVROWB + kb),
                 (const char*)(Kh + bh + (size_t)(tk0 + r) * D_) + kb);
        }
#pragma unroll
        for (int j = 0; j < 2; ++j) {
            int c = tid + j * 256;
            int r = c >> 3;
            int kb = (c & 7) * 16;
            cp16(Vs2 + (uint32_t)(r * KVROWB + kb),
                 (const char*)(Vh + bh + (size_t)(tk0 + r) * D_) + kb);
        }
    };

    const int c_start = (i == 0) ? 128 : 0;
    const int nch = (256 - c_start) / 64;

#pragma unroll
    for (int j = 0; j < 4; ++j) {
        int c = tid + j * 256;
        int r = c >> 3;
        int kb = (c & 7) * 16;
        cp16(Qs + (uint32_t)(r * QROWB + kb),
             (const char*)(Qh + bh + (size_t)(qrow0 + r) * D_) + kb);
    }
    load_kv(c_start, 0);
    CP_COMMIT();
    asm volatile("cp.async.wait_group 0;" ::: "memory");
    __syncthreads();

    uint32_t aq[4][4];
#pragma unroll
    for (int ks = 0; ks < 4; ++ks)
        LDSM4(aq[ks], Qs + (uint32_t)((rbase + (lane & 15)) * QROWB
                                      + (lane >> 4) * 16 + ks * 32));

    float o[8][4];
#pragma unroll
    for (int dnt = 0; dnt < 8; ++dnt)
#pragma unroll
        for (int e = 0; e < 4; ++e) o[dnt][e] = 0.0f;
    float l0 = 0.0f, l1 = 0.0f;

    const int r0loc = rbase + (lane >> 2);

    for (int it = 0; it < nch; ++it) {
        const int c0 = c_start + it * 64;
        if (it + 1 < nch) { load_kv(c0 + 64, (it + 1) & 1); CP_COMMIT(); }
        if (it > 0) {
            if (it + 1 < nch) asm volatile("cp.async.wait_group 1;" ::: "memory");
            else              asm volatile("cp.async.wait_group 0;" ::: "memory");
            __syncthreads();
        }
        const uint32_t Ks  = KVs + (uint32_t)(it & 1) * SWSTAGE;
        const uint32_t Vs2 = Ks + KVTILE;

        bool pok[4];
#pragma unroll
        for (int p = 0; p < 4; ++p)
            pok[p] = (c0 + 16 * p + 15 >= rbase) && (c0 + 16 * p <= rbase + 15 + 128);

        float s[8][4];
#pragma unroll
        for (int nt = 0; nt < 8; ++nt)
            if (pok[nt >> 1]) { s[nt][0]=0; s[nt][1]=0; s[nt][2]=0; s[nt][3]=0; }
#pragma unroll
        for (int ks = 0; ks < 4; ++ks) {
#pragma unroll
            for (int p = 0; p < 4; ++p) {
                if (!pok[p]) continue;
                uint32_t kb[4];
                LDSM4(kb, Ks + (uint32_t)(((lane & 7) + ((lane >> 4) & 1) * 8 + p * 16) * KVROWB
                                          + ((lane >> 3) & 1) * 16 + ks * 32));
                MMAF16(s[2 * p],     aq[ks], kb[0], kb[1]);
                MMAF16(s[2 * p + 1], aq[ks], kb[2], kb[3]);
            }
        }

        // mask (single unsigned cmp: 0 <= cc-rr <= 128), p = exp(s), pack, sums
        uint32_t ap[4][4];
#pragma unroll
        for (int t = 0; t < 4; ++t) { ap[t][0]=0; ap[t][1]=0; ap[t][2]=0; ap[t][3]=0; }
#pragma unroll
        for (int nt = 0; nt < 8; ++nt) {
            if (!pok[nt >> 1]) continue;
            int cb = c0 + 8 * nt + 2 * (lane & 3);
#pragma unroll
            for (int e = 0; e < 4; ++e) {
                int cc = cb + (e & 1);
                int rr = r0loc + (e >> 1) * 8;
                bool v = (unsigned)(cc - rr) <= 128u;
                s[nt][e] = v ? s[nt][e] : -1e30f;
            }
            float p0 = __expf(s[nt][0]);
            float p1 = __expf(s[nt][1]);
            float p2 = __expf(s[nt][2]);
            float p3 = __expf(s[nt][3]);
            l0 += p0 + p1; l1 += p2 + p3;
            int t  = nt >> 1;
            int hi = (nt & 1) * 2;
            ap[t][hi]     = h2_to_u32(__floats2half2_rn(p0, p1));
            ap[t][hi + 1] = h2_to_u32(__floats2half2_rn(p2, p3));
        }

#pragma unroll
        for (int t = 0; t < 4; ++t) {
            if (!pok[t]) continue;
#pragma unroll
            for (int g = 0; g < 4; ++g) {
                uint32_t vb[4];
                LDSM4T(vb, Vs2 + (uint32_t)((16 * t + (lane & 15)) * KVROWB
                                            + (g * 16 + ((lane >> 4) & 1) * 8) * 2));
                MMAF16(o[2 * g],     ap[t], vb[0], vb[1]);
                MMAF16(o[2 * g + 1], ap[t], vb[2], vb[3]);
            }
        }

        __syncthreads();
    }

    l0 += __shfl_xor_sync(0xFFFFFFFFu, l0, 1);
    l0 += __shfl_xor_sync(0xFFFFFFFFu, l0, 2);
    l1 += __shfl_xor_sync(0xFFFFFFFFu, l1, 1);
    l1 += __shfl_xor_sync(0xFFFFFFFFu, l1, 2);
    const float inv0 = 1.0f / l0;
    const float inv1 = 1.0f / l1;
    const int rg0 = qrow0 + r0loc;
#pragma unroll
    for (int dnt = 0; dnt < 8; ++dnt) {
        int dcol = 8 * dnt + 2 * (lane & 3);
        *(__half2*)(Oh + bh + (size_t)rg0 * D_ + dcol) =
            __floats2half2_rn(o[dnt][0] * inv0, o[dnt][1] * inv0);
        *(__half2*)(Oh + bh + (size_t)(rg0 + 8) * D_ + dcol) =
            __floats2half2_rn(o[dnt][2] * inv1, o[dnt][3] * inv1);
    }
}

// ---------------------------------------------------------------------------
// Launch
// ---------------------------------------------------------------------------
extern "C" void kernel_launch(void* const* d_in, const int* in_sizes, int n_in,
                              void* d_out, int out_size)
{
    const float* x  = (const float*)d_in[0];
    float* out = (float*)d_out;

    __half *qkv, *xh, *aoh, *wh;
    cudaGetSymbolAddress((void**)&qkv, g_qkv);
    cudaGetSymbolAddress((void**)&xh,  g_xh);
    cudaGetSymbolAddress((void**)&aoh, g_aoh);
    cudaGetSymbolAddress((void**)&wh,  g_wh);

    cudaFuncSetAttribute(gemm_qkv, cudaFuncAttributeMaxDynamicSharedMemorySize, GSMEM);
    cudaFuncSetAttribute(gemm_out, cudaFuncAttributeMaxDynamicSharedMemorySize, GSMEM);
    cudaFuncSetAttribute(swa_tc,   cudaFuncAttributeMaxDynamicSharedMemorySize, SWSMEM);

    const int nX  = M_ * D_;
    const int nW  = D_ * D_;
    const int thr = 256;

    // one conversion launch: x + 4 weights (x has 4x the elements; grid.x sized
    // for x, weight jobs bound-check out)
    ConvJobs jobs;
    jobs.j[0] = { (const float4*)x,       (__half2*)xh,                    nX / 4 };
    jobs.j[1] = { (const float4*)d_in[1], (__half2*)(wh + 0 * (size_t)nW), nW / 4 };
    jobs.j[2] = { (const float4*)d_in[2], (__half2*)(wh + 1 * (size_t)nW), nW / 4 };
    jobs.j[3] = { (const float4*)d_in[3], (__half2*)(wh + 2 * (size_t)nW), nW / 4 };
    jobs.j[4] = { (const float4*)d_in[4], (__half2*)(wh + 3 * (size_t)nW), nW / 4 };
    dim3 gc((nX / 4 + thr - 1) / thr, 5);
    conv_all_kernel<<<gc, thr>>>(jobs);

    dim3 gq(D_ / 64, M_ / 128, 3);      // fused Q,K,V
    gemm_qkv<<<gq, 128, GSMEM>>>(xh, wh, qkv, M_, D_, D_);

    dim3 ga(NB, H_, B_);
    swa_tc<<<ga, 256, SWSMEM>>>(qkv + 0 * (size_t)nX,
                                qkv + 1 * (size_t)nX,
                                qkv + 2 * (size_t)nX, aoh);

    dim3 gg(D_ / 64, M_ / 128);
    gemm_out<<<gg, 128, GSMEM>>>(aoh, wh + 3 * (size_t)nW, out, M_, D_, D_);
}